// round 15
// baseline (speedup 1.0000x reference)
#include <cuda_runtime.h>
#include <math.h>
#include <stdint.h>

#define B_ROWS 384
#define F_DIM  1024
#define GAMMA_C 1.0e4f
#define S_BF   (B_ROWS * F_DIM)
#define KSPLIT 6
#define TSTR   20                       // smem row stride in floats (16 data + 4 pad)
#define TILE_B (128 * TSTR * 4)         // 10240 bytes per tile
#define STG_B  (4 * TILE_B)             // Ah,Al,Bh,Bl per stage: 40960 bytes
#define SMEM_DYN (2 * STG_B)            // 81920 bytes

// -------- device scratch (no allocations) --------
__device__ float g_p1[KSPLIT * S_BF];
__device__ float g_p2[KSPLIT * S_BF];
__device__ int   g_amax[B_ROWS];
__device__ float g_hval[B_ROWS];
__device__ int   g_count[F_DIM];
__device__ float g_list[F_DIM * B_ROWS];

// ---------------- helpers ----------------
__device__ __forceinline__ uint32_t smem_u32(const void* p) {
    uint32_t a;
    asm("{ .reg .u64 t; cvta.to.shared.u64 t, %1; cvt.u32.u64 %0, t; }" : "=r"(a) : "l"(p));
    return a;
}
__device__ __forceinline__ void cvt_hilo(float x, float& h, float& l) {
    uint32_t hb, lb;
    asm("cvt.rna.tf32.f32 %0, %1;" : "=r"(hb) : "f"(x));
    h = __uint_as_float(hb);
    float r = x - h;
    asm("cvt.rna.tf32.f32 %0, %1;" : "=r"(lb) : "f"(r));
    l = __uint_as_float(lb);
}
__device__ __forceinline__ void ldsm4(uint32_t* r, uint32_t addr) {
    asm volatile("ldmatrix.sync.aligned.m8n8.x4.shared.b16 {%0,%1,%2,%3}, [%4];"
        : "=r"(r[0]), "=r"(r[1]), "=r"(r[2]), "=r"(r[3]) : "r"(addr));
}
__device__ __forceinline__ void mma_tf32(float* d, const uint32_t* a, uint32_t b0, uint32_t b1) {
    asm volatile("mma.sync.aligned.m16n8k8.row.col.f32.tf32.tf32.f32 "
        "{%0,%1,%2,%3}, {%4,%5,%6,%7}, {%8,%9}, {%0,%1,%2,%3};"
        : "+f"(d[0]), "+f"(d[1]), "+f"(d[2]), "+f"(d[3])
        : "r"(a[0]), "r"(a[1]), "r"(a[2]), "r"(a[3]), "r"(b0), "r"(b1));
}

// ---------------- warp-specialized 3xTF32 mma.sync GEMM (NT).
// CTA tile 128x128, 256 threads: warps 0-3 consumers (64x64 tiles, ldsm+mma only),
// warps 4-7 producers (LDG + tf32 hi/lo convert into 2-stage smem buffer).
// One __syncthreads per chunk is the stage handshake.
// C_partial[z][i,f] = sum_{k in z range} A[i,k] * W[f,k]
// WHICH=1: A = concat(x|m) (split at k=1024), dest g_p1.
// WHICH=2: A = h1 computed INLINE as relu(sum_z g_p1 + b1) (A1 = b1), dest g_p2.
template<int WHICH>
__global__ void __launch_bounds__(256) gemm_mma(const float* __restrict__ A1,
                                                const float* __restrict__ A2,
                                                const float* __restrict__ W, int K)
{
    extern __shared__ __align__(16) char dsm[];

    const int tid  = threadIdx.x;       // 256
    const int lane = tid & 31;
    const int wid  = tid >> 5;          // 0..7
    const bool consumer = (wid < 4);
    const int bx = blockIdx.x;          // N tile (8)
    const int by = blockIdx.y;          // M tile (3)
    const int z  = blockIdx.z;          // K split (6)

    const int chunks_total = K / 16;
    const int cbase = chunks_total / KSPLIT;
    const int crem  = chunks_total % KSPLIT;
    const int nch   = cbase + (z < crem ? 1 : 0);
    const int cstart = z * cbase + (z < crem ? z : crem);

    const uint32_t sbase = smem_u32(dsm);

    if (consumer) {
        // ---------------- consumer: 64x64 warp tile, pure ldsm+mma
        const int wm = wid >> 1;        // 0..1 -> m offset wm*64
        const int wn = wid & 1;         // 0..1 -> n offset wn*64
        const int sub = lane >> 3, rr = lane & 7;
        const uint32_t a_off = ((uint32_t)((wm * 64 + (sub & 1) * 8 + rr) * TSTR + (sub >> 1) * 4)) * 4u;
        const uint32_t b_off = ((uint32_t)((wn * 64 + (sub >> 1) * 8 + rr) * TSTR + (sub & 1) * 4)) * 4u;

        float acc[4][8][4];
#pragma unroll
        for (int i = 0; i < 4; i++)
#pragma unroll
            for (int j = 0; j < 8; j++)
#pragma unroll
                for (int q = 0; q < 4; q++) acc[i][j][q] = 0.0f;

        __syncthreads();   // wait for producer prologue (stage 0 filled)

        for (int c = 0; c < nch; c++) {
            const uint32_t stg = sbase + (uint32_t)(c & 1) * STG_B;
            const uint32_t Ahb = stg, Alb = stg + TILE_B, Bhb = stg + 2 * TILE_B, Blb = stg + 3 * TILE_B;
#pragma unroll
            for (int ks = 0; ks < 2; ks++) {
                uint32_t Ah[4][4], Al[4][4], Bh[4][4], Bl[4][4];
                const uint32_t kso = (uint32_t)(ks * 32);
#pragma unroll
                for (int mt = 0; mt < 4; mt++) {
                    ldsm4(Ah[mt], Ahb + a_off + mt * (16 * TSTR * 4) + kso);
                    ldsm4(Al[mt], Alb + a_off + mt * (16 * TSTR * 4) + kso);
                }
#pragma unroll
                for (int p = 0; p < 4; p++) {
                    ldsm4(Bh[p], Bhb + b_off + p * (16 * TSTR * 4) + kso);
                    ldsm4(Bl[p], Blb + b_off + p * (16 * TSTR * 4) + kso);
                }
#pragma unroll
                for (int mt = 0; mt < 4; mt++) {
#pragma unroll
                    for (int nt = 0; nt < 8; nt++) {
                        const uint32_t* bh = &Bh[nt >> 1][(nt & 1) * 2];
                        const uint32_t* bl = &Bl[nt >> 1][(nt & 1) * 2];
                        mma_tf32(acc[mt][nt], Ah[mt], bh[0], bh[1]);   // hi*hi
                        mma_tf32(acc[mt][nt], Ah[mt], bl[0], bl[1]);   // hi*lo
                        mma_tf32(acc[mt][nt], Al[mt], bh[0], bh[1]);   // lo*hi
                    }
                }
            }
            __syncthreads();   // mma(c) done; producer may overwrite stage (c&1) next iter
        }

        // ---- epilogue: write partials
        float* P = (WHICH == 1 ? g_p1 : g_p2) + (size_t)z * S_BF;
        const int g = lane >> 2, tig = lane & 3;
#pragma unroll
        for (int mt = 0; mt < 4; mt++) {
            const int row0 = by * 128 + wm * 64 + mt * 16 + g;
#pragma unroll
            for (int nt = 0; nt < 8; nt++) {
                const int col0 = bx * 128 + wn * 64 + nt * 8 + tig * 2;
                *reinterpret_cast<float2*>(P + (size_t)row0 * F_DIM + col0) =
                    make_float2(acc[mt][nt][0], acc[mt][nt][1]);
                *reinterpret_cast<float2*>(P + (size_t)(row0 + 8) * F_DIM + col0) =
                    make_float2(acc[mt][nt][2], acc[mt][nt][3]);
            }
        }
    } else {
        // ---------------- producer: LDG (+ inline combine for WHICH=2) + convert + store
        const int ptid = tid - 128;     // 0..127
        float4 pa[4], pb[4];

        auto load_chunk = [&](int c) {
            const int kb = (cstart + c) * 16;
#pragma unroll
            for (int it = 0; it < 4; it++) {
                const int f4 = it * 128 + ptid;
                const int row = f4 >> 2, c4 = f4 & 3;
                if (WHICH == 1) {
                    const float* Ab; int kc;
                    if (kb < 1024) { Ab = A1; kc = kb; } else { Ab = A2; kc = kb - 1024; }
                    pa[it] = *reinterpret_cast<const float4*>(Ab + (size_t)(by * 128 + row) * F_DIM + kc + c4 * 4);
                } else {
                    // h1 = relu(sum_z p1 + b1), computed inline (same add order as combine1)
                    const size_t base = (size_t)(by * 128 + row) * F_DIM + kb + c4 * 4;
                    float4 v = *reinterpret_cast<const float4*>(g_p1 + base);
#pragma unroll
                    for (int zz = 1; zz < KSPLIT; zz++) {
                        const float4 p = *reinterpret_cast<const float4*>(g_p1 + (size_t)zz * S_BF + base);
                        v.x += p.x; v.y += p.y; v.z += p.z; v.w += p.w;
                    }
                    const float4 bb = *reinterpret_cast<const float4*>(A1 + kb + c4 * 4);
                    v.x = fmaxf(v.x + bb.x, 0.0f);
                    v.y = fmaxf(v.y + bb.y, 0.0f);
                    v.z = fmaxf(v.z + bb.z, 0.0f);
                    v.w = fmaxf(v.w + bb.w, 0.0f);
                    pa[it] = v;
                }
                pb[it] = *reinterpret_cast<const float4*>(W + (size_t)(bx * 128 + row) * K + kb + c4 * 4);
            }
        };
        auto store_chunk = [&](int s) {
            char* stgp = dsm + (size_t)s * STG_B;
#pragma unroll
            for (int it = 0; it < 4; it++) {
                const int f4 = it * 128 + ptid;
                const int row = f4 >> 2, c4 = f4 & 3;
                const int off = (row * TSTR + c4 * 4) * 4;
                float4 h, l;
                cvt_hilo(pa[it].x, h.x, l.x); cvt_hilo(pa[it].y, h.y, l.y);
                cvt_hilo(pa[it].z, h.z, l.z); cvt_hilo(pa[it].w, h.w, l.w);
                *reinterpret_cast<float4*>(stgp + off) = h;
                *reinterpret_cast<float4*>(stgp + TILE_B + off) = l;
                cvt_hilo(pb[it].x, h.x, l.x); cvt_hilo(pb[it].y, h.y, l.y);
                cvt_hilo(pb[it].z, h.z, l.z); cvt_hilo(pb[it].w, h.w, l.w);
                *reinterpret_cast<float4*>(stgp + 2 * TILE_B + off) = h;
                *reinterpret_cast<float4*>(stgp + 3 * TILE_B + off) = l;
            }
        };

        load_chunk(0);
        store_chunk(0);
        if (nch > 1) load_chunk(1);
        __syncthreads();   // stage 0 ready

        for (int c = 0; c < nch; c++) {
            if (c + 1 < nch) {
                store_chunk((c + 1) & 1);       // regs hold chunk c+1
                if (c + 2 < nch) load_chunk(c + 2);
            }
            __syncthreads();
        }
    }
}

// ---------------- combine GEMM2 partials + bias + gumbel -> argmax + softmax-at-max
__global__ void row_softmax_argmax(const float* __restrict__ b2,
                                   const float* __restrict__ gumbel)
{
    const int r = blockIdx.x;
    const int tid = threadIdx.x;  // 256
    const int lane = tid & 31, warp = tid >> 5;
    __shared__ float t[F_DIM];
    __shared__ float sv[8];
    __shared__ int   si[8];
    __shared__ float s_mx; __shared__ int s_ix;

    const size_t b4 = (size_t)r * (F_DIM / 4);
    {
        float4 v = reinterpret_cast<const float4*>(g_p2)[b4 + tid];
#pragma unroll
        for (int zz = 1; zz < KSPLIT; zz++) {
            const float4 p = reinterpret_cast<const float4*>(g_p2 + (size_t)zz * S_BF)[b4 + tid];
            v.x += p.x; v.y += p.y; v.z += p.z; v.w += p.w;
        }
        const float4 bb = reinterpret_cast<const float4*>(b2)[tid];
        const float4 gg = reinterpret_cast<const float4*>(gumbel)[b4 + tid];
        v.x += bb.x + gg.x; v.y += bb.y + gg.y; v.z += bb.z + gg.z; v.w += bb.w + gg.w;
        reinterpret_cast<float4*>(t)[tid] = v;
    }
    __syncthreads();

    // argmax (first-occurrence tie-break) via warp shuffles
    float bv = -3.402823466e38f; int bi = 0;
    for (int f = tid; f < F_DIM; f += 256) {
        float v = t[f];
        if (v > bv) { bv = v; bi = f; }
    }
#pragma unroll
    for (int off = 16; off > 0; off >>= 1) {
        float ov = __shfl_down_sync(0xFFFFFFFFu, bv, off);
        int   oi = __shfl_down_sync(0xFFFFFFFFu, bi, off);
        if (ov > bv || (ov == bv && oi < bi)) { bv = ov; bi = oi; }
    }
    if (lane == 0) { sv[warp] = bv; si[warp] = bi; }
    __syncthreads();
    if (warp == 0) {
        bv = (lane < 8) ? sv[lane] : -3.402823466e38f;
        bi = (lane < 8) ? si[lane] : 0;
#pragma unroll
        for (int off = 4; off > 0; off >>= 1) {
            float ov = __shfl_down_sync(0xFFFFFFFFu, bv, off);
            int   oi = __shfl_down_sync(0xFFFFFFFFu, bi, off);
            if (ov > bv || (ov == bv && oi < bi)) { bv = ov; bi = oi; }
        }
        if (lane == 0) { s_mx = bv; s_ix = bi; }
    }
    __syncthreads();
    const float mx = s_mx;

    float lsum = 0.0f;
    for (int f = tid; f < F_DIM; f += 256) lsum += expf(t[f] - mx);
#pragma unroll
    for (int off = 16; off > 0; off >>= 1) lsum += __shfl_down_sync(0xFFFFFFFFu, lsum, off);
    if (lane == 0) sv[warp] = lsum;
    __syncthreads();
    if (tid == 0) {
        float tot = 0.0f;
#pragma unroll
        for (int w = 0; w < 8; w++) tot += sv[w];
        g_amax[r] = s_ix;
        float smax = 1.0f / tot;
        g_hval[r] = __fadd_rn(__fadd_rn(1.0f, -smax), smax);  // (1 - s) + s in fp32
    }
}

// ---------------- invert argmax: per-feature count + deterministic hval list
__global__ void build_lists()
{
    __shared__ int sa[B_ROWS];
    const int tid = threadIdx.x; // 1024
    if (tid < B_ROWS) sa[tid] = g_amax[tid];
    __syncthreads();
    if (tid < F_DIM) {
        int c = 0;
        for (int j = 0; j < B_ROWS; j++) c += (sa[j] == tid) ? 1 : 0;
        g_count[tid] = c;
    }
    if (tid < B_ROWS) {
        int a = sa[tid];
        int slot = 0;
        for (int j = 0; j < tid; j++) slot += (sa[j] == a) ? 1 : 0;
        g_list[(size_t)a * B_ROWS + slot] = g_hval[tid];
    }
}

// ---------------- final: pr[i,f] = aB*(B*q0 + corrections) + beta
// grid (384, 4) x 256 threads: one f per thread -> max MLP on the W3 gather.
__global__ void final_kernel(const float* __restrict__ W3, const float* __restrict__ b3,
                             float* __restrict__ out, float aB, float beta)
{
    const int i = blockIdx.x;
    const int f = blockIdx.y * 256 + threadIdx.x;
    const float hvi = g_hval[i];
    const int ai = g_amax[i];

    float z = __fmul_rn(hvi, __ldg(W3 + (size_t)f * F_DIM + ai)) + b3[f];
    float q0 = 1.0f / (1.0f + GAMMA_C * z * z);
    float acc = 384.0f * q0;
    int c = g_count[f];
    for (int s = 0; s < c; s++) {
        float d = z - g_list[(size_t)f * B_ROWS + s];
        acc += 1.0f / (1.0f + GAMMA_C * d * d) - q0;
    }
    out[(size_t)i * F_DIM + f] = aB * acc + beta;
}

extern "C" void kernel_launch(void* const* d_in, const int* in_sizes, int n_in,
                              void* d_out, int out_size)
{
    const float* x      = (const float*)d_in[0];
    const float* m      = (const float*)d_in[1];
    const float* gumbel = (const float*)d_in[2];
    const float* W1     = (const float*)d_in[3];
    const float* b1     = (const float*)d_in[4];
    const float* W2     = (const float*)d_in[5];
    const float* b2     = (const float*)d_in[6];
    const float* W3     = (const float*)d_in[7];
    const float* b3     = (const float*)d_in[8];
    float* out = (float*)d_out;

    // alpha/beta exactly as _prob (float64 then cast)
    double s = 0.0;
    for (int k = 1; k <= B_ROWS - 1; k++) s += 1.0 / (double)k;
    double theta = 1.0 / s;
    float alpha = (float)((double)B_ROWS / ((double)B_ROWS + theta));
    float beta  = (float)(0.5 * theta / ((double)B_ROWS + theta));
    float aB    = alpha / (float)B_ROWS;

    cudaFuncSetAttribute(gemm_mma<1>, cudaFuncAttributeMaxDynamicSharedMemorySize, SMEM_DYN);
    cudaFuncSetAttribute(gemm_mma<2>, cudaFuncAttributeMaxDynamicSharedMemorySize, SMEM_DYN);

    // GEMM1: partials of [x|m] @ W1^T   M=384, N=1024, K=2048, split-K=6 (grid 144)
    gemm_mma<1><<<dim3(8, 3, KSPLIT), 256, SMEM_DYN>>>(x, m, W1, 2048);

    // GEMM2: partials of h1 @ W2^T, h1 combined inline from g_p1 (+b1, relu)
    gemm_mma<2><<<dim3(8, 3, KSPLIT), 256, SMEM_DYN>>>(b1, nullptr, W2, 1024);

    row_softmax_argmax<<<B_ROWS, 256>>>(b2, gumbel);
    build_lists<<<1, 1024>>>();
    final_kernel<<<dim3(B_ROWS, 4), 256>>>(W3, b3, out, aB, beta);
}

// round 16
// speedup vs baseline: 1.0937x; 1.0937x over previous
#include <cuda_runtime.h>
#include <math.h>
#include <stdint.h>

#define B_ROWS 384
#define F_DIM  1024
#define GAMMA_C 1.0e4f
#define S_BF   (B_ROWS * F_DIM)
#define KSPLIT 6
#define TSTR   20                       // smem row stride in floats (16 data + 4 pad)
#define TILE_B (128 * TSTR * 4)         // 10240 bytes per tile
#define STG_B  (4 * TILE_B)             // Ah,Al,Bh,Bl per stage: 40960 bytes
#define SMEM_DYN (2 * STG_B)            // 81920 bytes

// -------- device scratch (no allocations) --------
__device__ float g_h1[S_BF];
__device__ float g_p1[KSPLIT * S_BF];
__device__ float g_p2[KSPLIT * S_BF];
__device__ int   g_amax[B_ROWS];
__device__ float g_hval[B_ROWS];
__device__ int   g_count[F_DIM];
__device__ float g_list[F_DIM * B_ROWS];

// ---------------- helpers ----------------
__device__ __forceinline__ uint32_t smem_u32(const void* p) {
    uint32_t a;
    asm("{ .reg .u64 t; cvta.to.shared.u64 t, %1; cvt.u32.u64 %0, t; }" : "=r"(a) : "l"(p));
    return a;
}
__device__ __forceinline__ void cvt_hilo(float x, float& h, float& l) {
    uint32_t hb, lb;
    asm("cvt.rna.tf32.f32 %0, %1;" : "=r"(hb) : "f"(x));
    h = __uint_as_float(hb);
    float r = x - h;
    asm("cvt.rna.tf32.f32 %0, %1;" : "=r"(lb) : "f"(r));
    l = __uint_as_float(lb);
}
__device__ __forceinline__ void ldsm4(uint32_t* r, uint32_t addr) {
    asm volatile("ldmatrix.sync.aligned.m8n8.x4.shared.b16 {%0,%1,%2,%3}, [%4];"
        : "=r"(r[0]), "=r"(r[1]), "=r"(r[2]), "=r"(r[3]) : "r"(addr));
}
__device__ __forceinline__ void mma_tf32(float* d, const uint32_t* a, uint32_t b0, uint32_t b1) {
    asm volatile("mma.sync.aligned.m16n8k8.row.col.f32.tf32.tf32.f32 "
        "{%0,%1,%2,%3}, {%4,%5,%6,%7}, {%8,%9}, {%0,%1,%2,%3};"
        : "+f"(d[0]), "+f"(d[1]), "+f"(d[2]), "+f"(d[3])
        : "r"(a[0]), "r"(a[1]), "r"(a[2]), "r"(a[3]), "r"(b0), "r"(b1));
}

// ---------------- warp-specialized 3xTF32 mma.sync GEMM (NT).
// CTA tile 128x128, 256 threads: warps 0-3 consumers (64x64 tiles, ldsm+mma only),
// warps 4-7 producers (LDG + tf32 hi/lo convert into 2-stage smem buffer).
// One __syncthreads per chunk is the stage handshake.
// C_partial[z][i,f] = sum_{k in z range} A[i,k] * W[f,k]
// WHICH=1: A = concat(x|m) (split at k=1024), dest g_p1.  WHICH=2: A = g_h1, dest g_p2.
template<int WHICH>
__global__ void __launch_bounds__(256) gemm_mma(const float* __restrict__ A1,
                                                const float* __restrict__ A2,
                                                const float* __restrict__ W, int K)
{
    extern __shared__ __align__(16) char dsm[];

    const int tid  = threadIdx.x;       // 256
    const int lane = tid & 31;
    const int wid  = tid >> 5;          // 0..7
    const bool consumer = (wid < 4);
    const int bx = blockIdx.x;          // N tile (8)
    const int by = blockIdx.y;          // M tile (3)
    const int z  = blockIdx.z;          // K split (6)

    const int chunks_total = K / 16;
    const int cbase = chunks_total / KSPLIT;
    const int crem  = chunks_total % KSPLIT;
    const int nch   = cbase + (z < crem ? 1 : 0);
    const int cstart = z * cbase + (z < crem ? z : crem);

    const uint32_t sbase = smem_u32(dsm);

    if (consumer) {
        // ---------------- consumer: 64x64 warp tile, pure ldsm+mma
        const int wm = wid >> 1;        // 0..1 -> m offset wm*64
        const int wn = wid & 1;         // 0..1 -> n offset wn*64
        const int sub = lane >> 3, rr = lane & 7;
        const uint32_t a_off = ((uint32_t)((wm * 64 + (sub & 1) * 8 + rr) * TSTR + (sub >> 1) * 4)) * 4u;
        const uint32_t b_off = ((uint32_t)((wn * 64 + (sub >> 1) * 8 + rr) * TSTR + (sub & 1) * 4)) * 4u;

        float acc[4][8][4];
#pragma unroll
        for (int i = 0; i < 4; i++)
#pragma unroll
            for (int j = 0; j < 8; j++)
#pragma unroll
                for (int q = 0; q < 4; q++) acc[i][j][q] = 0.0f;

        __syncthreads();   // wait for producer prologue (stage 0 filled)

        for (int c = 0; c < nch; c++) {
            const uint32_t stg = sbase + (uint32_t)(c & 1) * STG_B;
            const uint32_t Ahb = stg, Alb = stg + TILE_B, Bhb = stg + 2 * TILE_B, Blb = stg + 3 * TILE_B;
#pragma unroll
            for (int ks = 0; ks < 2; ks++) {
                uint32_t Ah[4][4], Al[4][4], Bh[4][4], Bl[4][4];
                const uint32_t kso = (uint32_t)(ks * 32);
#pragma unroll
                for (int mt = 0; mt < 4; mt++) {
                    ldsm4(Ah[mt], Ahb + a_off + mt * (16 * TSTR * 4) + kso);
                    ldsm4(Al[mt], Alb + a_off + mt * (16 * TSTR * 4) + kso);
                }
#pragma unroll
                for (int p = 0; p < 4; p++) {
                    ldsm4(Bh[p], Bhb + b_off + p * (16 * TSTR * 4) + kso);
                    ldsm4(Bl[p], Blb + b_off + p * (16 * TSTR * 4) + kso);
                }
#pragma unroll
                for (int mt = 0; mt < 4; mt++) {
#pragma unroll
                    for (int nt = 0; nt < 8; nt++) {
                        const uint32_t* bh = &Bh[nt >> 1][(nt & 1) * 2];
                        const uint32_t* bl = &Bl[nt >> 1][(nt & 1) * 2];
                        mma_tf32(acc[mt][nt], Ah[mt], bh[0], bh[1]);   // hi*hi
                        mma_tf32(acc[mt][nt], Ah[mt], bl[0], bl[1]);   // hi*lo
                        mma_tf32(acc[mt][nt], Al[mt], bh[0], bh[1]);   // lo*hi
                    }
                }
            }
            __syncthreads();   // mma(c) done; producer may overwrite stage (c&1) next iter
        }

        // ---- epilogue: write partials
        float* P = (WHICH == 1 ? g_p1 : g_p2) + (size_t)z * S_BF;
        const int g = lane >> 2, tig = lane & 3;
#pragma unroll
        for (int mt = 0; mt < 4; mt++) {
            const int row0 = by * 128 + wm * 64 + mt * 16 + g;
#pragma unroll
            for (int nt = 0; nt < 8; nt++) {
                const int col0 = bx * 128 + wn * 64 + nt * 8 + tig * 2;
                *reinterpret_cast<float2*>(P + (size_t)row0 * F_DIM + col0) =
                    make_float2(acc[mt][nt][0], acc[mt][nt][1]);
                *reinterpret_cast<float2*>(P + (size_t)(row0 + 8) * F_DIM + col0) =
                    make_float2(acc[mt][nt][2], acc[mt][nt][3]);
            }
        }
    } else {
        // ---------------- producer: LDG + convert + store
        const int ptid = tid - 128;     // 0..127
        float4 pa[4], pb[4];

        auto load_chunk = [&](int c) {
            const int kb = (cstart + c) * 16;
#pragma unroll
            for (int it = 0; it < 4; it++) {
                const int f4 = it * 128 + ptid;
                const int row = f4 >> 2, c4 = f4 & 3;
                const float* Ab; int kc;
                if (WHICH == 1) { if (kb < 1024) { Ab = A1; kc = kb; } else { Ab = A2; kc = kb - 1024; } }
                else            { Ab = g_h1; kc = kb; }
                pa[it] = *reinterpret_cast<const float4*>(Ab + (size_t)(by * 128 + row) * F_DIM + kc + c4 * 4);
                pb[it] = *reinterpret_cast<const float4*>(W + (size_t)(bx * 128 + row) * K + kb + c4 * 4);
            }
        };
        auto store_chunk = [&](int s) {
            char* stgp = dsm + (size_t)s * STG_B;
#pragma unroll
            for (int it = 0; it < 4; it++) {
                const int f4 = it * 128 + ptid;
                const int row = f4 >> 2, c4 = f4 & 3;
                const int off = (row * TSTR + c4 * 4) * 4;
                float4 h, l;
                cvt_hilo(pa[it].x, h.x, l.x); cvt_hilo(pa[it].y, h.y, l.y);
                cvt_hilo(pa[it].z, h.z, l.z); cvt_hilo(pa[it].w, h.w, l.w);
                *reinterpret_cast<float4*>(stgp + off) = h;
                *reinterpret_cast<float4*>(stgp + TILE_B + off) = l;
                cvt_hilo(pb[it].x, h.x, l.x); cvt_hilo(pb[it].y, h.y, l.y);
                cvt_hilo(pb[it].z, h.z, l.z); cvt_hilo(pb[it].w, h.w, l.w);
                *reinterpret_cast<float4*>(stgp + 2 * TILE_B + off) = h;
                *reinterpret_cast<float4*>(stgp + 3 * TILE_B + off) = l;
            }
        };

        load_chunk(0);
        store_chunk(0);
        if (nch > 1) load_chunk(1);
        __syncthreads();   // stage 0 ready

        for (int c = 0; c < nch; c++) {
            if (c + 1 < nch) {
                store_chunk((c + 1) & 1);       // regs hold chunk c+1
                if (c + 2 < nch) load_chunk(c + 2);
            }
            __syncthreads();
        }
    }
}

// ---------------- combine GEMM1 partials: h1 = relu(sum_z p1 + b1[col])
__global__ void combine1(const float* __restrict__ b1)
{
    const int i4 = blockIdx.x * 256 + threadIdx.x;   // 98304 float4
    float4 r = reinterpret_cast<const float4*>(g_p1)[i4];
#pragma unroll
    for (int zz = 1; zz < KSPLIT; zz++) {
        const float4 p = reinterpret_cast<const float4*>(g_p1 + (size_t)zz * S_BF)[i4];
        r.x += p.x; r.y += p.y; r.z += p.z; r.w += p.w;
    }
    const float4 bb = reinterpret_cast<const float4*>(b1)[i4 & 255];
    r.x = fmaxf(r.x + bb.x, 0.0f);
    r.y = fmaxf(r.y + bb.y, 0.0f);
    r.z = fmaxf(r.z + bb.z, 0.0f);
    r.w = fmaxf(r.w + bb.w, 0.0f);
    reinterpret_cast<float4*>(g_h1)[i4] = r;
}

// ---------------- combine GEMM2 partials + bias + gumbel -> argmax + softmax-at-max
__global__ void row_softmax_argmax(const float* __restrict__ b2,
                                   const float* __restrict__ gumbel)
{
    const int r = blockIdx.x;
    const int tid = threadIdx.x;  // 256
    const int lane = tid & 31, warp = tid >> 5;
    __shared__ float t[F_DIM];
    __shared__ float sv[8];
    __shared__ int   si[8];
    __shared__ float s_mx; __shared__ int s_ix;

    const size_t b4 = (size_t)r * (F_DIM / 4);
    {
        float4 v = reinterpret_cast<const float4*>(g_p2)[b4 + tid];
#pragma unroll
        for (int zz = 1; zz < KSPLIT; zz++) {
            const float4 p = reinterpret_cast<const float4*>(g_p2 + (size_t)zz * S_BF)[b4 + tid];
            v.x += p.x; v.y += p.y; v.z += p.z; v.w += p.w;
        }
        const float4 bb = reinterpret_cast<const float4*>(b2)[tid];
        const float4 gg = reinterpret_cast<const float4*>(gumbel)[b4 + tid];
        v.x += bb.x + gg.x; v.y += bb.y + gg.y; v.z += bb.z + gg.z; v.w += bb.w + gg.w;
        reinterpret_cast<float4*>(t)[tid] = v;
    }
    __syncthreads();

    // argmax (first-occurrence tie-break) via warp shuffles
    float bv = -3.402823466e38f; int bi = 0;
    for (int f = tid; f < F_DIM; f += 256) {
        float v = t[f];
        if (v > bv) { bv = v; bi = f; }
    }
#pragma unroll
    for (int off = 16; off > 0; off >>= 1) {
        float ov = __shfl_down_sync(0xFFFFFFFFu, bv, off);
        int   oi = __shfl_down_sync(0xFFFFFFFFu, bi, off);
        if (ov > bv || (ov == bv && oi < bi)) { bv = ov; bi = oi; }
    }
    if (lane == 0) { sv[warp] = bv; si[warp] = bi; }
    __syncthreads();
    if (warp == 0) {
        bv = (lane < 8) ? sv[lane] : -3.402823466e38f;
        bi = (lane < 8) ? si[lane] : 0;
#pragma unroll
        for (int off = 4; off > 0; off >>= 1) {
            float ov = __shfl_down_sync(0xFFFFFFFFu, bv, off);
            int   oi = __shfl_down_sync(0xFFFFFFFFu, bi, off);
            if (ov > bv || (ov == bv && oi < bi)) { bv = ov; bi = oi; }
        }
        if (lane == 0) { s_mx = bv; s_ix = bi; }
    }
    __syncthreads();
    const float mx = s_mx;

    float lsum = 0.0f;
    for (int f = tid; f < F_DIM; f += 256) lsum += expf(t[f] - mx);
#pragma unroll
    for (int off = 16; off > 0; off >>= 1) lsum += __shfl_down_sync(0xFFFFFFFFu, lsum, off);
    if (lane == 0) sv[warp] = lsum;
    __syncthreads();
    if (tid == 0) {
        float tot = 0.0f;
#pragma unroll
        for (int w = 0; w < 8; w++) tot += sv[w];
        g_amax[r] = s_ix;
        float smax = 1.0f / tot;
        g_hval[r] = __fadd_rn(__fadd_rn(1.0f, -smax), smax);  // (1 - s) + s in fp32
    }
}

// ---------------- invert argmax, PARALLEL: grid 5 x 256 threads.
// Blocks 0-3: count[f] for f = b*256 + tid.  Block 4: deterministic slot lists.
__global__ void build_lists_par()
{
    __shared__ int   sa[B_ROWS];
    __shared__ float sh[B_ROWS];
    const int tid = threadIdx.x;  // 256
    const int b = blockIdx.x;     // 0..4
    for (int j = tid; j < B_ROWS; j += 256) {
        sa[j] = g_amax[j];
        sh[j] = g_hval[j];
    }
    __syncthreads();

    if (b < 4) {
        const int f = b * 256 + tid;
        int c = 0;
        for (int j = 0; j < B_ROWS; j++) c += (sa[j] == f) ? 1 : 0;
        g_count[f] = c;
    } else {
        for (int r = tid; r < B_ROWS; r += 256) {
            int a = sa[r];
            int slot = 0;
            for (int j = 0; j < r; j++) slot += (sa[j] == a) ? 1 : 0;
            g_list[(size_t)a * B_ROWS + slot] = sh[r];
        }
    }
}

// ---------------- final: pr[i,f] = aB*(B*q0 + corrections) + beta
// grid (384, 4) x 256 threads: one f per thread -> max MLP on the W3 gather.
__global__ void final_kernel(const float* __restrict__ W3, const float* __restrict__ b3,
                             float* __restrict__ out, float aB, float beta)
{
    const int i = blockIdx.x;
    const int f = blockIdx.y * 256 + threadIdx.x;
    const float hvi = g_hval[i];
    const int ai = g_amax[i];

    float z = __fmul_rn(hvi, __ldg(W3 + (size_t)f * F_DIM + ai)) + b3[f];
    float q0 = 1.0f / (1.0f + GAMMA_C * z * z);
    float acc = 384.0f * q0;
    int c = g_count[f];
    for (int s = 0; s < c; s++) {
        float d = z - g_list[(size_t)f * B_ROWS + s];
        acc += 1.0f / (1.0f + GAMMA_C * d * d) - q0;
    }
    out[(size_t)i * F_DIM + f] = aB * acc + beta;
}

extern "C" void kernel_launch(void* const* d_in, const int* in_sizes, int n_in,
                              void* d_out, int out_size)
{
    const float* x      = (const float*)d_in[0];
    const float* m      = (const float*)d_in[1];
    const float* gumbel = (const float*)d_in[2];
    const float* W1     = (const float*)d_in[3];
    const float* b1     = (const float*)d_in[4];
    const float* W2     = (const float*)d_in[5];
    const float* b2     = (const float*)d_in[6];
    const float* W3     = (const float*)d_in[7];
    const float* b3     = (const float*)d_in[8];
    float* out = (float*)d_out;

    // alpha/beta exactly as _prob (float64 then cast)
    double s = 0.0;
    for (int k = 1; k <= B_ROWS - 1; k++) s += 1.0 / (double)k;
    double theta = 1.0 / s;
    float alpha = (float)((double)B_ROWS / ((double)B_ROWS + theta));
    float beta  = (float)(0.5 * theta / ((double)B_ROWS + theta));
    float aB    = alpha / (float)B_ROWS;

    cudaFuncSetAttribute(gemm_mma<1>, cudaFuncAttributeMaxDynamicSharedMemorySize, SMEM_DYN);
    cudaFuncSetAttribute(gemm_mma<2>, cudaFuncAttributeMaxDynamicSharedMemorySize, SMEM_DYN);

    // GEMM1: partials of [x|m] @ W1^T   M=384, N=1024, K=2048, split-K=6 (grid 144)
    gemm_mma<1><<<dim3(8, 3, KSPLIT), 256, SMEM_DYN>>>(x, m, W1, 2048);
    combine1<<<384, 256>>>(b1);

    // GEMM2: partials of h1 @ W2^T      M=384, N=1024, K=1024, split-K=6
    gemm_mma<2><<<dim3(8, 3, KSPLIT), 256, SMEM_DYN>>>(nullptr, nullptr, W2, 1024);

    row_softmax_argmax<<<B_ROWS, 256>>>(b2, gumbel);
    build_lists_par<<<5, 256>>>();
    final_kernel<<<dim3(B_ROWS, 4), 256>>>(W3, b3, out, aB, beta);
}

// round 17
// speedup vs baseline: 1.3459x; 1.2306x over previous
#include <cuda_runtime.h>
#include <cuda_bf16.h>
#include <math.h>
#include <stdint.h>

#define B_ROWS 384
#define F_DIM  1024
#define GAMMA_C 1.0e4f
#define S_BF   (B_ROWS * F_DIM)
#define KSPLIT 6
#define RSTR_B 80                       // smem row stride in bytes (32 bf16 data + 8 pad)
#define TILE_B (128 * RSTR_B)           // 10240 bytes per term tile
#define STG_B  (4 * TILE_B)             // A0,A1,B0,B1 per stage: 40960 bytes
#define SMEM_DYN (2 * STG_B)            // 81920 bytes

// -------- device scratch (no allocations) --------
__device__ float g_h1[S_BF];
__device__ float g_p1[KSPLIT * S_BF];
__device__ float g_p2[KSPLIT * S_BF];
__device__ int   g_amax[B_ROWS];
__device__ float g_hval[B_ROWS];
__device__ int   g_count[F_DIM];
__device__ float g_list[F_DIM * B_ROWS];

// ---------------- helpers ----------------
__device__ __forceinline__ uint32_t smem_u32(const void* p) {
    uint32_t a;
    asm("{ .reg .u64 t; cvta.to.shared.u64 t, %1; cvt.u32.u64 %0, t; }" : "=r"(a) : "l"(p));
    return a;
}
// pack two floats to bf16x2 (lo, hi) with rn rounding
__device__ __forceinline__ uint32_t pack_bf16x2(float lo, float hi) {
    uint32_t r;
    asm("cvt.rn.bf16x2.f32 %0, %1, %2;" : "=r"(r) : "f"(hi), "f"(lo));
    return r;
}
__device__ __forceinline__ void ldsm4(uint32_t* r, uint32_t addr) {
    asm volatile("ldmatrix.sync.aligned.m8n8.x4.shared.b16 {%0,%1,%2,%3}, [%4];"
        : "=r"(r[0]), "=r"(r[1]), "=r"(r[2]), "=r"(r[3]) : "r"(addr));
}
__device__ __forceinline__ void mma_bf16(float* d, const uint32_t* a, uint32_t b0, uint32_t b1) {
    asm volatile("mma.sync.aligned.m16n8k16.row.col.f32.bf16.bf16.f32 "
        "{%0,%1,%2,%3}, {%4,%5,%6,%7}, {%8,%9}, {%0,%1,%2,%3};"
        : "+f"(d[0]), "+f"(d[1]), "+f"(d[2]), "+f"(d[3])
        : "r"(a[0]), "r"(a[1]), "r"(a[2]), "r"(a[3]), "r"(b0), "r"(b1));
}

// ---------------- warp-specialized 3xBF16 mma.sync GEMM (NT).
// CTA tile 128x128, K-chunk 32. 256 threads: warps 0-3 consumers (64x64 tiles,
// ldsm+mma only), warps 4-7 producers (LDG + bf16 2-term split into 2-stage smem).
// x*y ~= b0c0 + b0c1 + b1c0 (drops b1c1 ~ 2^-18) with fp32 accumulation.
// C_partial[z][i,f] = sum_{k in z range} A[i,k] * W[f,k]
// WHICH=1: A = concat(x|m) (split at k=1024), dest g_p1.  WHICH=2: A = g_h1, dest g_p2.
template<int WHICH>
__global__ void __launch_bounds__(256) gemm_mma(const float* __restrict__ A1,
                                                const float* __restrict__ A2,
                                                const float* __restrict__ W, int K)
{
    extern __shared__ __align__(16) char dsm[];

    const int tid  = threadIdx.x;       // 256
    const int lane = tid & 31;
    const int wid  = tid >> 5;          // 0..7
    const bool consumer = (wid < 4);
    const int bx = blockIdx.x;          // N tile (8)
    const int by = blockIdx.y;          // M tile (3)
    const int z  = blockIdx.z;          // K split (6)

    const int chunks_total = K / 32;
    const int cbase = chunks_total / KSPLIT;
    const int crem  = chunks_total % KSPLIT;
    const int nch   = cbase + (z < crem ? 1 : 0);
    const int cstart = z * cbase + (z < crem ? z : crem);

    const uint32_t sbase = smem_u32(dsm);

    if (consumer) {
        // ---------------- consumer: 64x64 warp tile, pure ldsm+mma
        const int wm = wid >> 1;        // 0..1 -> m offset wm*64
        const int wn = wid & 1;         // 0..1 -> n offset wn*64
        // ldmatrix x4 source rows: lanes 0-7 -> rows+0..7 (klo), 8-15 -> rows+8..15 (klo),
        // 16-23 -> rows+0..7 (khi), 24-31 -> rows+8..15 (khi)
        const uint32_t a_off = (uint32_t)(wm * 64 + (lane & 7) + ((lane >> 3) & 1) * 8) * RSTR_B
                             + (uint32_t)(lane >> 4) * 16;
        const uint32_t b_off = (uint32_t)(wn * 64 + (lane & 7) + ((lane >> 3) & 1) * 8) * RSTR_B
                             + (uint32_t)(lane >> 4) * 16;

        float acc[4][8][4];
#pragma unroll
        for (int i = 0; i < 4; i++)
#pragma unroll
            for (int j = 0; j < 8; j++)
#pragma unroll
                for (int q = 0; q < 4; q++) acc[i][j][q] = 0.0f;

        __syncthreads();   // wait for producer prologue (stage 0 filled)

        for (int c = 0; c < nch; c++) {
            const uint32_t stg = sbase + (uint32_t)(c & 1) * STG_B;
            const uint32_t A0b = stg, A1b = stg + TILE_B, B0b = stg + 2 * TILE_B, B1b = stg + 3 * TILE_B;
#pragma unroll
            for (int ks = 0; ks < 2; ks++) {           // 2 k16 steps per 32-chunk
                uint32_t A0f[4][4], A1f[4][4], B0f[4][4], B1f[4][4];
                const uint32_t kso = (uint32_t)(ks * 32);   // 16 bf16 = 32 bytes
#pragma unroll
                for (int mt = 0; mt < 4; mt++) {
                    ldsm4(A0f[mt], A0b + a_off + mt * (16 * RSTR_B) + kso);
                    ldsm4(A1f[mt], A1b + a_off + mt * (16 * RSTR_B) + kso);
                }
#pragma unroll
                for (int ng = 0; ng < 4; ng++) {
                    ldsm4(B0f[ng], B0b + b_off + ng * (16 * RSTR_B) + kso);
                    ldsm4(B1f[ng], B1b + b_off + ng * (16 * RSTR_B) + kso);
                }
#pragma unroll
                for (int mt = 0; mt < 4; mt++) {
#pragma unroll
                    for (int nt = 0; nt < 8; nt++) {
                        const int ng = nt >> 1, h = nt & 1;
                        mma_bf16(acc[mt][nt], A0f[mt], B0f[ng][h], B0f[ng][h + 2]);  // b0*c0
                        mma_bf16(acc[mt][nt], A0f[mt], B1f[ng][h], B1f[ng][h + 2]);  // b0*c1
                        mma_bf16(acc[mt][nt], A1f[mt], B0f[ng][h], B0f[ng][h + 2]);  // b1*c0
                    }
                }
            }
            __syncthreads();   // mma(c) done; producer may overwrite stage (c&1) next iter
        }

        // ---- epilogue: write partials
        float* P = (WHICH == 1 ? g_p1 : g_p2) + (size_t)z * S_BF;
        const int g = lane >> 2, tig = lane & 3;
#pragma unroll
        for (int mt = 0; mt < 4; mt++) {
            const int row0 = by * 128 + wm * 64 + mt * 16 + g;
#pragma unroll
            for (int nt = 0; nt < 8; nt++) {
                const int col0 = bx * 128 + wn * 64 + nt * 8 + tig * 2;
                *reinterpret_cast<float2*>(P + (size_t)row0 * F_DIM + col0) =
                    make_float2(acc[mt][nt][0], acc[mt][nt][1]);
                *reinterpret_cast<float2*>(P + (size_t)(row0 + 8) * F_DIM + col0) =
                    make_float2(acc[mt][nt][2], acc[mt][nt][3]);
            }
        }
    } else {
        // ---------------- producer: LDG + bf16 2-term split + store
        const int ptid = tid - 128;     // 0..127
        float4 pa[8], pb[8];

        auto load_chunk = [&](int c) {
            const int kb = (cstart + c) * 32;
#pragma unroll
            for (int it = 0; it < 8; it++) {
                const int f4 = it * 128 + ptid;     // 0..1023
                const int row = f4 >> 3, c4 = f4 & 7;
                const float* Ab; int kc;
                if (WHICH == 1) { if (kb < 1024) { Ab = A1; kc = kb; } else { Ab = A2; kc = kb - 1024; } }
                else            { Ab = g_h1; kc = kb; }
                pa[it] = *reinterpret_cast<const float4*>(Ab + (size_t)(by * 128 + row) * F_DIM + kc + c4 * 4);
                pb[it] = *reinterpret_cast<const float4*>(W + (size_t)(bx * 128 + row) * K + kb + c4 * 4);
            }
        };
        auto split_store = [&](float4 v, char* t0, char* t1, int off) {
            uint2 p0, p1;
            p0.x = pack_bf16x2(v.x, v.y);
            p0.y = pack_bf16x2(v.z, v.w);
            float f0 = __uint_as_float(p0.x << 16);
            float f1 = __uint_as_float(p0.x & 0xFFFF0000u);
            float f2 = __uint_as_float(p0.y << 16);
            float f3 = __uint_as_float(p0.y & 0xFFFF0000u);
            p1.x = pack_bf16x2(v.x - f0, v.y - f1);
            p1.y = pack_bf16x2(v.z - f2, v.w - f3);
            *reinterpret_cast<uint2*>(t0 + off) = p0;
            *reinterpret_cast<uint2*>(t1 + off) = p1;
        };
        auto store_chunk = [&](int s) {
            char* stgp = dsm + (size_t)s * STG_B;
#pragma unroll
            for (int it = 0; it < 8; it++) {
                const int f4 = it * 128 + ptid;
                const int row = f4 >> 3, c4 = f4 & 7;
                const int off = row * RSTR_B + c4 * 8;   // 4 bf16 = 8 bytes
                split_store(pa[it], stgp,              stgp + TILE_B,     off);
                split_store(pb[it], stgp + 2 * TILE_B, stgp + 3 * TILE_B, off);
            }
        };

        load_chunk(0);
        store_chunk(0);
        if (nch > 1) load_chunk(1);
        __syncthreads();   // stage 0 ready

        for (int c = 0; c < nch; c++) {
            if (c + 1 < nch) {
                store_chunk((c + 1) & 1);       // regs hold chunk c+1
                if (c + 2 < nch) load_chunk(c + 2);
            }
            __syncthreads();
        }
    }
}

// ---------------- combine GEMM1 partials: h1 = relu(sum_z p1 + b1[col])
__global__ void combine1(const float* __restrict__ b1)
{
    const int i4 = blockIdx.x * 256 + threadIdx.x;   // 98304 float4
    float4 r = reinterpret_cast<const float4*>(g_p1)[i4];
#pragma unroll
    for (int zz = 1; zz < KSPLIT; zz++) {
        const float4 p = reinterpret_cast<const float4*>(g_p1 + (size_t)zz * S_BF)[i4];
        r.x += p.x; r.y += p.y; r.z += p.z; r.w += p.w;
    }
    const float4 bb = reinterpret_cast<const float4*>(b1)[i4 & 255];
    r.x = fmaxf(r.x + bb.x, 0.0f);
    r.y = fmaxf(r.y + bb.y, 0.0f);
    r.z = fmaxf(r.z + bb.z, 0.0f);
    r.w = fmaxf(r.w + bb.w, 0.0f);
    reinterpret_cast<float4*>(g_h1)[i4] = r;
}

// ---------------- combine GEMM2 partials + bias + gumbel -> argmax + softmax-at-max
__global__ void row_softmax_argmax(const float* __restrict__ b2,
                                   const float* __restrict__ gumbel)
{
    const int r = blockIdx.x;
    const int tid = threadIdx.x;  // 256
    const int lane = tid & 31, warp = tid >> 5;
    __shared__ float t[F_DIM];
    __shared__ float sv[8];
    __shared__ int   si[8];
    __shared__ float s_mx; __shared__ int s_ix;

    const size_t b4 = (size_t)r * (F_DIM / 4);
    {
        float4 v = reinterpret_cast<const float4*>(g_p2)[b4 + tid];
#pragma unroll
        for (int zz = 1; zz < KSPLIT; zz++) {
            const float4 p = reinterpret_cast<const float4*>(g_p2 + (size_t)zz * S_BF)[b4 + tid];
            v.x += p.x; v.y += p.y; v.z += p.z; v.w += p.w;
        }
        const float4 bb = reinterpret_cast<const float4*>(b2)[tid];
        const float4 gg = reinterpret_cast<const float4*>(gumbel)[b4 + tid];
        v.x += bb.x + gg.x; v.y += bb.y + gg.y; v.z += bb.z + gg.z; v.w += bb.w + gg.w;
        reinterpret_cast<float4*>(t)[tid] = v;
    }
    __syncthreads();

    // argmax (first-occurrence tie-break) via warp shuffles
    float bv = -3.402823466e38f; int bi = 0;
    for (int f = tid; f < F_DIM; f += 256) {
        float v = t[f];
        if (v > bv) { bv = v; bi = f; }
    }
#pragma unroll
    for (int off = 16; off > 0; off >>= 1) {
        float ov = __shfl_down_sync(0xFFFFFFFFu, bv, off);
        int   oi = __shfl_down_sync(0xFFFFFFFFu, bi, off);
        if (ov > bv || (ov == bv && oi < bi)) { bv = ov; bi = oi; }
    }
    if (lane == 0) { sv[warp] = bv; si[warp] = bi; }
    __syncthreads();
    if (warp == 0) {
        bv = (lane < 8) ? sv[lane] : -3.402823466e38f;
        bi = (lane < 8) ? si[lane] : 0;
#pragma unroll
        for (int off = 4; off > 0; off >>= 1) {
            float ov = __shfl_down_sync(0xFFFFFFFFu, bv, off);
            int   oi = __shfl_down_sync(0xFFFFFFFFu, bi, off);
            if (ov > bv || (ov == bv && oi < bi)) { bv = ov; bi = oi; }
        }
        if (lane == 0) { s_mx = bv; s_ix = bi; }
    }
    __syncthreads();
    const float mx = s_mx;

    float lsum = 0.0f;
    for (int f = tid; f < F_DIM; f += 256) lsum += expf(t[f] - mx);
#pragma unroll
    for (int off = 16; off > 0; off >>= 1) lsum += __shfl_down_sync(0xFFFFFFFFu, lsum, off);
    if (lane == 0) sv[warp] = lsum;
    __syncthreads();
    if (tid == 0) {
        float tot = 0.0f;
#pragma unroll
        for (int w = 0; w < 8; w++) tot += sv[w];
        g_amax[r] = s_ix;
        float smax = 1.0f / tot;
        g_hval[r] = __fadd_rn(__fadd_rn(1.0f, -smax), smax);  // (1 - s) + s in fp32
    }
}

// ---------------- invert argmax, PARALLEL: grid 5 x 256 threads.
// Blocks 0-3: count[f] for f = b*256 + tid.  Block 4: deterministic slot lists.
__global__ void build_lists_par()
{
    __shared__ int   sa[B_ROWS];
    __shared__ float sh[B_ROWS];
    const int tid = threadIdx.x;  // 256
    const int b = blockIdx.x;     // 0..4
    for (int j = tid; j < B_ROWS; j += 256) {
        sa[j] = g_amax[j];
        sh[j] = g_hval[j];
    }
    __syncthreads();

    if (b < 4) {
        const int f = b * 256 + tid;
        int c = 0;
        for (int j = 0; j < B_ROWS; j++) c += (sa[j] == f) ? 1 : 0;
        g_count[f] = c;
    } else {
        for (int r = tid; r < B_ROWS; r += 256) {
            int a = sa[r];
            int slot = 0;
            for (int j = 0; j < r; j++) slot += (sa[j] == a) ? 1 : 0;
            g_list[(size_t)a * B_ROWS + slot] = sh[r];
        }
    }
}

// ---------------- final: pr[i,f] = aB*(B*q0 + corrections) + beta
// grid (384, 4) x 256 threads: one f per thread -> max MLP on the W3 gather.
__global__ void final_kernel(const float* __restrict__ W3, const float* __restrict__ b3,
                             float* __restrict__ out, float aB, float beta)
{
    const int i = blockIdx.x;
    const int f = blockIdx.y * 256 + threadIdx.x;
    const float hvi = g_hval[i];
    const int ai = g_amax[i];

    float z = __fmul_rn(hvi, __ldg(W3 + (size_t)f * F_DIM + ai)) + b3[f];
    float q0 = 1.0f / (1.0f + GAMMA_C * z * z);
    float acc = 384.0f * q0;
    int c = g_count[f];
    for (int s = 0; s < c; s++) {
        float d = z - g_list[(size_t)f * B_ROWS + s];
        acc += 1.0f / (1.0f + GAMMA_C * d * d) - q0;
    }
    out[(size_t)i * F_DIM + f] = aB * acc + beta;
}

extern "C" void kernel_launch(void* const* d_in, const int* in_sizes, int n_in,
                              void* d_out, int out_size)
{
    const float* x      = (const float*)d_in[0];
    const float* m      = (const float*)d_in[1];
    const float* gumbel = (const float*)d_in[2];
    const float* W1     = (const float*)d_in[3];
    const float* b1     = (const float*)d_in[4];
    const float* W2     = (const float*)d_in[5];
    const float* b2     = (const float*)d_in[6];
    const float* W3     = (const float*)d_in[7];
    const float* b3     = (const float*)d_in[8];
    float* out = (float*)d_out;

    // alpha/beta exactly as _prob (float64 then cast)
    double s = 0.0;
    for (int k = 1; k <= B_ROWS - 1; k++) s += 1.0 / (double)k;
    double theta = 1.0 / s;
    float alpha = (float)((double)B_ROWS / ((double)B_ROWS + theta));
    float beta  = (float)(0.5 * theta / ((double)B_ROWS + theta));
    float aB    = alpha / (float)B_ROWS;

    cudaFuncSetAttribute(gemm_mma<1>, cudaFuncAttributeMaxDynamicSharedMemorySize, SMEM_DYN);
    cudaFuncSetAttribute(gemm_mma<2>, cudaFuncAttributeMaxDynamicSharedMemorySize, SMEM_DYN);

    // GEMM1: partials of [x|m] @ W1^T   M=384, N=1024, K=2048, split-K=6 (grid 144)
    gemm_mma<1><<<dim3(8, 3, KSPLIT), 256, SMEM_DYN>>>(x, m, W1, 2048);
    combine1<<<384, 256>>>(b1);

    // GEMM2: partials of h1 @ W2^T      M=384, N=1024, K=1024, split-K=6
    gemm_mma<2><<<dim3(8, 3, KSPLIT), 256, SMEM_DYN>>>(nullptr, nullptr, W2, 1024);

    row_softmax_argmax<<<B_ROWS, 256>>>(b2, gumbel);
    build_lists_par<<<5, 256>>>();
    final_kernel<<<dim3(B_ROWS, 4), 256>>>(W3, b3, out, aB, beta);
}